// round 3
// baseline (speedup 1.0000x reference)
#include <cuda_runtime.h>
#include <cstdint>

#define T     2048
#define E     512
#define HD    512
#define G4    2048   /* 4*HD */
#define TAGS  32
#define START 30
#define STOP  31
#define NEGV  (-10000.0f)

#define CANARY 0xFFFFFFFFu

// ---------------- scratch (device globals; no allocation) ----------------
__device__ float g_x[T * E];          // gathered embeddings          4 MB
__device__ float g_xg[2][T * G4];     // precomputed input gates     32 MB
__device__ float g_h[2][T * HD];      // LSTM hidden outputs          8 MB
__device__ float g_feats[T * TAGS];   // emissions                  256 KB

// ---------------- gather + poison fused ----------------
__global__ void k_prep(const int* __restrict__ sent, const float* __restrict__ emb) {
    int blk = blockIdx.x;
    if (blk < T) {
        // embedding gather: one row per block
        const float4* src = (const float4*)(emb + (size_t)sent[blk] * E);
        ((float4*)(g_x + (size_t)blk * E))[threadIdx.x] = src[threadIdx.x];
    } else {
        // poison g_h: blocks T..T+2047, each covers 1024 floats (128 thr x 8)
        int cb = blk - T;
        unsigned* dst = (unsigned*)g_h + (size_t)cb * 1024 + threadIdx.x * 8;
        uint4 v = {CANARY, CANARY, CANARY, CANARY};
        *(uint4*)(dst)     = v;
        *(uint4*)(dst + 4) = v;
    }
}

// ---------------- packed f32x2 helpers ----------------
#define FMA2(acc, a, b) asm("fma.rn.f32x2 %0, %1, %2, %0;" : "+l"(acc) : "l"(a), "l"(b))
#define ADD2(acc, b)    asm("add.rn.f32x2 %0, %0, %1;" : "+l"(acc) : "l"(b))
#define PACK2(out, lo, hi) asm("mov.b64 %0, {%1, %2};" : "=l"(out) : "f"(lo), "f"(hi))

// ---------------- input GEMM: g_xg[d] = g_x @ W_ih[d]^T + b[d] (FFMA2) -------
#define BM 128
#define BN 128
#define BK 16
__global__ void __launch_bounds__(256) k_gemm(const float* __restrict__ w_ih_f,
                                              const float* __restrict__ b_f,
                                              const float* __restrict__ w_ih_b,
                                              const float* __restrict__ b_b) {
    int d = blockIdx.z;
    const float* W    = d ? w_ih_b : w_ih_f;
    const float* bias = d ? b_b    : b_f;

    __shared__ float As[BK][BM];
    __shared__ float Bs[BK][BN];

    int tid = threadIdx.x;
    int tx = tid & 15, ty = tid >> 4;
    int t0 = blockIdx.y * BM, r0 = blockIdx.x * BN;

    unsigned long long acc2[8][4];
#pragma unroll
    for (int i = 0; i < 8; i++)
#pragma unroll
        for (int j = 0; j < 4; j++) acc2[i][j] = 0ull;

    int lm = tid >> 2;            // 0..63
    int lk = (tid & 3) * 4;       // 0,4,8,12

    for (int k0 = 0; k0 < E; k0 += BK) {
#pragma unroll
        for (int rep = 0; rep < 2; rep++) {
            float4 v = *(const float4*)(g_x + (size_t)(t0 + lm + rep * 64) * E + k0 + lk);
            As[lk + 0][lm + rep * 64] = v.x;
            As[lk + 1][lm + rep * 64] = v.y;
            As[lk + 2][lm + rep * 64] = v.z;
            As[lk + 3][lm + rep * 64] = v.w;
            float4 w = *(const float4*)(W + (size_t)(r0 + lm + rep * 64) * E + k0 + lk);
            Bs[lk + 0][lm + rep * 64] = w.x;
            Bs[lk + 1][lm + rep * 64] = w.y;
            Bs[lk + 2][lm + rep * 64] = w.z;
            Bs[lk + 3][lm + rep * 64] = w.w;
        }
        __syncthreads();
#pragma unroll
        for (int k = 0; k < BK; k++) {
            float a[8];
            *(float4*)(a)     = *(const float4*)&As[k][ty * 8];
            *(float4*)(a + 4) = *(const float4*)&As[k][ty * 8 + 4];
            ulonglong2 bl = *(const ulonglong2*)&Bs[k][tx * 8];
            ulonglong2 bh = *(const ulonglong2*)&Bs[k][tx * 8 + 4];
            unsigned long long bq[4] = {bl.x, bl.y, bh.x, bh.y};
#pragma unroll
            for (int i = 0; i < 8; i++) {
                unsigned long long ad;
                PACK2(ad, a[i], a[i]);
                FMA2(acc2[i][0], ad, bq[0]);
                FMA2(acc2[i][1], ad, bq[1]);
                FMA2(acc2[i][2], ad, bq[2]);
                FMA2(acc2[i][3], ad, bq[3]);
            }
        }
        __syncthreads();
    }

    float* out = g_xg[d];
#pragma unroll
    for (int i = 0; i < 8; i++) {
        int t = t0 + ty * 8 + i;
#pragma unroll
        for (int jp = 0; jp < 4; jp += 2) {
            int r = r0 + tx * 8 + jp * 2;
            float4 v;
            v.x = __uint_as_float((unsigned)(acc2[i][jp]     & 0xFFFFFFFFull)) + bias[r + 0];
            v.y = __uint_as_float((unsigned)(acc2[i][jp]     >> 32))           + bias[r + 1];
            v.z = __uint_as_float((unsigned)(acc2[i][jp + 1] & 0xFFFFFFFFull)) + bias[r + 2];
            v.w = __uint_as_float((unsigned)(acc2[i][jp + 1] >> 32))           + bias[r + 3];
            *(float4*)(out + (size_t)t * G4 + r) = v;
        }
    }
}

// ---------------- persistent bidirectional LSTM recurrence ----------------
// 128 CTAs x 256 threads (8 warps). CTA (d*64+b), warp w owns h-row b*8+w of
// direction d. Lane = gate*8 + seg. Each warp is a self-contained pipeline:
// poll full h[t-1] (16 contiguous floats/lane, 4xv4 MLP), stage to padded
// double-buffered smem, packed-f32x2 dot, shfl-xor reduce over segs, gather
// gates via idx-shfl, activation (replicated), lane0 publishes 1 float.
// No block syncs, no named barriers.
__device__ __forceinline__ float sig_f(float x) { return 1.f / (1.f + __expf(-x)); }
__device__ __forceinline__ float tanh_f(float x) { return 1.f - 2.f / (__expf(2.f * x) + 1.f); }

#define SEGP 68   /* padded floats per 64-col segment: conflict-free LDS */

__global__ void __launch_bounds__(256, 1) k_lstm(const float* __restrict__ w_hh_f,
                                                 const float* __restrict__ w_hh_b,
                                                 const float* __restrict__ h0,
                                                 const float* __restrict__ c0) {
    int cta = blockIdx.x;
    int d = cta >> 6;
    int b = cta & 63;
    const float* Whh = d ? w_hh_b : w_hh_f;

    int tid  = threadIdx.x;
    int w    = tid >> 5;            // warp = local h-row
    int lane = tid & 31;
    int gate = lane >> 3, seg = lane & 7;
    int row  = b * 8 + w;            // global h index this warp produces
    int grow = gate * HD + row;      // gate row in W_hh / xg

    // W_hh segment into registers as packed f32 pairs
    unsigned long long wq[32];
    {
        const ulonglong2* wr = (const ulonglong2*)(Whh + (size_t)grow * HD + seg * 64);
#pragma unroll
        for (int m = 0; m < 16; m++) {
            ulonglong2 v = wr[m];
            wq[2 * m] = v.x; wq[2 * m + 1] = v.y;
        }
    }

    // double-buffered padded staging: [warp][buf][8 segs * SEGP]
    __shared__ float sh[8][2][8 * SEGP];

    const float* xg = g_xg[d];
    float* hout = g_h[d];

    float c = __ldg(c0 + d * HD + row);   // replicated across lanes

    // xg prefetch (only seg==0 lanes use it)
    int t0i = d ? (T - 1) : 0;
    float xg_cur = 0.f;
    if (seg == 0) xg_cur = __ldg(xg + (size_t)t0i * G4 + grow);

    // poll assignment: 16 contiguous floats per lane
    int pseg = lane >> 2;              // which 64-col segment I poll
    int poff = (lane & 3) * 16;        // offset within segment
    int pcol = pseg * 64 + poff;       // global h column base
    float* stage_base0 = &sh[w][0][pseg * SEGP + poff];
    float* stage_base1 = &sh[w][1][pseg * SEGP + poff];

    for (int s = 0; s < T; s++) {
        int t = d ? (T - 1 - s) : s;
        int buf = s & 1;

        uint4 r0, r1, r2, r3;
        if (s == 0) {
            const uint4* hp = (const uint4*)(h0 + d * HD + pcol);
            r0 = hp[0]; r1 = hp[1]; r2 = hp[2]; r3 = hp[3];
        } else {
            int tp = d ? (t + 1) : (t - 1);
            const unsigned* hp = (const unsigned*)(hout + (size_t)tp * HD + pcol);
            for (;;) {
                asm volatile("ld.volatile.global.v4.u32 {%0,%1,%2,%3}, [%4];"
                             : "=r"(r0.x), "=r"(r0.y), "=r"(r0.z), "=r"(r0.w) : "l"(hp));
                asm volatile("ld.volatile.global.v4.u32 {%0,%1,%2,%3}, [%4];"
                             : "=r"(r1.x), "=r"(r1.y), "=r"(r1.z), "=r"(r1.w) : "l"(hp + 4));
                asm volatile("ld.volatile.global.v4.u32 {%0,%1,%2,%3}, [%4];"
                             : "=r"(r2.x), "=r"(r2.y), "=r"(r2.z), "=r"(r2.w) : "l"(hp + 8));
                asm volatile("ld.volatile.global.v4.u32 {%0,%1,%2,%3}, [%4];"
                             : "=r"(r3.x), "=r"(r3.y), "=r"(r3.z), "=r"(r3.w) : "l"(hp + 12));
                bool bad = (r0.x == CANARY) | (r0.y == CANARY) | (r0.z == CANARY) | (r0.w == CANARY) |
                           (r1.x == CANARY) | (r1.y == CANARY) | (r1.z == CANARY) | (r1.w == CANARY) |
                           (r2.x == CANARY) | (r2.y == CANARY) | (r2.z == CANARY) | (r2.w == CANARY) |
                           (r3.x == CANARY) | (r3.y == CANARY) | (r3.z == CANARY) | (r3.w == CANARY);
                if (!bad) break;
            }
        }
        float* stage = buf ? stage_base1 : stage_base0;
        *(uint4*)(stage)      = r0;
        *(uint4*)(stage + 4)  = r1;
        *(uint4*)(stage + 8)  = r2;
        *(uint4*)(stage + 12) = r3;
        __syncwarp();

        // packed dot over my 64-col segment
        const ulonglong2* hq = (const ulonglong2*)&sh[w][buf][seg * SEGP];
        unsigned long long a0 = 0, a1 = 0, a2 = 0, a3 = 0;
#pragma unroll
        for (int m = 0; m < 16; m += 2) {
            ulonglong2 x = hq[m];
            ulonglong2 y = hq[m + 1];
            FMA2(a0, wq[2 * m],     x.x);
            FMA2(a1, wq[2 * m + 1], x.y);
            FMA2(a2, wq[2 * m + 2], y.x);
            FMA2(a3, wq[2 * m + 3], y.y);
        }
        ADD2(a0, a2);
        ADD2(a1, a3);
        ADD2(a0, a1);
        float part = __uint_as_float((unsigned)(a0 & 0xFFFFFFFFull)) +
                     __uint_as_float((unsigned)(a0 >> 32));

        float xg_use = xg_cur;
        if (seg == 0) {
            part += xg_use;
            if (s + 1 < T) {
                int tn = d ? (t - 1) : (t + 1);
                xg_cur = __ldg(xg + (size_t)tn * G4 + grow);
            }
        }

        unsigned m = 0xFFFFFFFFu;
        part += __shfl_xor_sync(m, part, 1);
        part += __shfl_xor_sync(m, part, 2);
        part += __shfl_xor_sync(m, part, 4);   // all lanes in 8-group hold gate total

        int base = lane & 7;
        float xi  = __shfl_sync(m, part, base);
        float xf  = __shfl_sync(m, part, 8 + base);
        float xgg = __shfl_sync(m, part, 16 + base);
        float xo  = __shfl_sync(m, part, 24 + base);

        c = sig_f(xf) * c + sig_f(xi) * tanh_f(xgg);
        float hnew = sig_f(xo) * tanh_f(c);
        if (lane == 0) {
            asm volatile("st.volatile.global.f32 [%0], %1;"
                         :: "l"(hout + (size_t)t * HD + row), "f"(hnew));
        }
    }
}

// ---------------- emissions: feats = [hf|hb] @ W_out^T + b_out ----------------
__global__ void k_feats(const float* __restrict__ W_out, const float* __restrict__ b_out) {
    int t = blockIdx.x;
    int tid = threadIdx.x;         // 128
    int tag = tid >> 2, q = tid & 3;
    const float* wrow = W_out + (size_t)tag * 1024 + q * 256;
    const float* hs = (q < 2) ? (g_h[0] + (size_t)t * HD + q * 256)
                              : (g_h[1] + (size_t)t * HD + (q - 2) * 256);
    float sum = 0.f;
#pragma unroll 8
    for (int k = 0; k < 256; k += 4) {
        float4 w4 = *(const float4*)(wrow + k);
        float4 h4 = *(const float4*)(hs + k);
        sum += w4.x * h4.x + w4.y * h4.y + w4.z * h4.z + w4.w * h4.w;
    }
    sum += __shfl_xor_sync(0xFFFFFFFFu, sum, 1);
    sum += __shfl_xor_sync(0xFFFFFFFFu, sum, 2);
    if (q == 0) g_feats[t * TAGS + tag] = sum + b_out[tag];
}

// ---------------- Viterbi (single warp; strict-greater first-max argmax) -----
// jnp.argmax semantics = first occurrence of the max. Ascending-j chains with
// strict > updates, merged in ascending chain order (ties keep lower chain).
extern __shared__ unsigned char vit_smem[];
__global__ void k_viterbi(const float* __restrict__ transitions, float* __restrict__ out,
                          int out_size) {
    unsigned char* bp = vit_smem;                    // T*TAGS bytes
    float* fvbuf = (float*)(vit_smem + T * TAGS);    // 2 * TAGS floats (ping-pong)
    int n = threadIdx.x;

    float tr[TAGS];
#pragma unroll
    for (int j = 0; j < TAGS; j++) tr[j] = transitions[n * TAGS + j];

    fvbuf[n] = (n == START) ? 0.f : NEGV;
    __syncwarp();

    float f0 = g_feats[0 * TAGS + n];
    float f1 = g_feats[1 * TAGS + n];

    for (int t = 0; t < T; t++) {
        const float* fv = fvbuf + (t & 1) * TAGS;
        float*       fw = fvbuf + ((t + 1) & 1) * TAGS;

        // 4 ascending chains of 8, strict-greater keeps first max
        float b0, b1, b2, b3;
        int   a0 = 0, a1 = 8, a2 = 16, a3 = 24;
        b0 = fv[0]  + tr[0];
        b1 = fv[8]  + tr[8];
        b2 = fv[16] + tr[16];
        b3 = fv[24] + tr[24];
#pragma unroll
        for (int j = 1; j < 8; j++) {
            float v0 = fv[j]      + tr[j];
            float v1 = fv[j + 8]  + tr[j + 8];
            float v2 = fv[j + 16] + tr[j + 16];
            float v3 = fv[j + 24] + tr[j + 24];
            if (v0 > b0) { b0 = v0; a0 = j; }
            if (v1 > b1) { b1 = v1; a1 = j + 8; }
            if (v2 > b2) { b2 = v2; a2 = j + 16; }
            if (v3 > b3) { b3 = v3; a3 = j + 24; }
        }
        // order-preserving merges (strict > keeps lower chain on ties)
        if (b1 > b0) { b0 = b1; a0 = a1; }
        if (b3 > b2) { b2 = b3; a2 = a3; }
        if (b2 > b0) { b0 = b2; a0 = a2; }

        float feat = (t & 1) ? f1 : f0;
        if (t + 2 < T) {
            float nf = g_feats[(t + 2) * TAGS + n];
            if (t & 1) f1 = nf; else f0 = nf;
        }
        bp[t * TAGS + n] = (unsigned char)a0;
        fw[n] = b0 + feat;
        __syncwarp();
    }

    const float* fvF = fvbuf + (T & 1) * TAGS;
    // terminal argmax: first max across lanes (exact)
    float term = fvF[n] + transitions[STOP * TAGS + n];
    int best = 0;
    {
        float bb = __shfl_sync(0xFFFFFFFFu, term, 0);
#pragma unroll
        for (int j = 1; j < TAGS; j++) {
            float v = __shfl_sync(0xFFFFFFFFu, term, j);
            if (v > bb) { bb = v; best = j; }
        }
    }
    float score = fvF[best] + transitions[STOP * TAGS + best];

    if (n == 0) {
        if (out_size >= T + 1) {
            out[0] = score;
            int tag = best;
            for (int t = T - 1; t >= 0; t--) {
                out[1 + t] = (float)tag;
                tag = bp[t * TAGS + tag];
            }
        } else if (out_size >= T) {
            int tag = best;
            for (int t = T - 1; t >= 0; t--) {
                out[t] = (float)tag;
                tag = bp[t * TAGS + tag];
            }
        } else {
            out[0] = score;
        }
    }
}

// ---------------- launch ----------------
extern "C" void kernel_launch(void* const* d_in, const int* in_sizes, int n_in,
                              void* d_out, int out_size) {
    const int*   sentence    = (const int*)d_in[0];
    const float* emb         = (const float*)d_in[1];
    const float* w_ih_f      = (const float*)d_in[2];
    const float* w_hh_f      = (const float*)d_in[3];
    const float* b_f         = (const float*)d_in[4];
    const float* w_ih_b      = (const float*)d_in[5];
    const float* w_hh_b      = (const float*)d_in[6];
    const float* b_b         = (const float*)d_in[7];
    const float* W_out       = (const float*)d_in[8];
    const float* b_out       = (const float*)d_in[9];
    const float* transitions = (const float*)d_in[10];
    const float* h0          = (const float*)d_in[11];
    const float* c0          = (const float*)d_in[12];
    float* out = (float*)d_out;

    k_prep<<<T + 2048, 128>>>(sentence, emb);
    k_gemm<<<dim3(16, 16, 2), 256>>>(w_ih_f, b_f, w_ih_b, b_b);
    k_lstm<<<128, 256>>>(w_hh_f, w_hh_b, h0, c0);
    k_feats<<<T, 128>>>(W_out, b_out);

    int vit_smem_bytes = T * TAGS + 2 * TAGS * (int)sizeof(float);
    cudaFuncSetAttribute(k_viterbi, cudaFuncAttributeMaxDynamicSharedMemorySize, vit_smem_bytes);
    k_viterbi<<<1, 32, vit_smem_bytes>>>(transitions, out, out_size);
}

// round 5
// speedup vs baseline: 9.5499x; 9.5499x over previous
#include <cuda_runtime.h>
#include <cstdint>

#define T     2048
#define E     512
#define HD    512
#define G4    2048   /* 4*HD */
#define TAGS  32
#define START 30
#define STOP  31
#define NEGV  (-10000.0f)

#define CANARY 0xFFFFFFFFu

// ---------------- scratch (device globals; no allocation) ----------------
__device__ float g_x[T * E];          // gathered embeddings          4 MB
__device__ float g_xg[2][T * G4];     // precomputed input gates     32 MB
__device__ float g_h[2][T * HD];      // LSTM hidden outputs          8 MB
__device__ float g_feats[T * TAGS];   // emissions                  256 KB

// ---------------- gather + poison fused ----------------
__global__ void k_prep(const int* __restrict__ sent, const float* __restrict__ emb) {
    int blk = blockIdx.x;
    if (blk < T) {
        const float4* src = (const float4*)(emb + (size_t)sent[blk] * E);
        ((float4*)(g_x + (size_t)blk * E))[threadIdx.x] = src[threadIdx.x];
    } else {
        int cb = blk - T;
        unsigned* dst = (unsigned*)g_h + (size_t)cb * 1024 + threadIdx.x * 8;
        uint4 v = {CANARY, CANARY, CANARY, CANARY};
        *(uint4*)(dst)     = v;
        *(uint4*)(dst + 4) = v;
    }
}

// ---------------- packed f32x2 helpers ----------------
#define FMA2(acc, a, b) asm("fma.rn.f32x2 %0, %1, %2, %0;" : "+l"(acc) : "l"(a), "l"(b))
#define ADD2(acc, b)    asm("add.rn.f32x2 %0, %0, %1;" : "+l"(acc) : "l"(b))
#define PACK2(out, lo, hi) asm("mov.b64 %0, {%1, %2};" : "=l"(out) : "f"(lo), "f"(hi))

// ---------------- input GEMM: g_xg[d] = g_x @ W_ih[d]^T + b[d] (FFMA2) -------
#define BM 128
#define BN 128
#define BK 16
__global__ void __launch_bounds__(256) k_gemm(const float* __restrict__ w_ih_f,
                                              const float* __restrict__ b_f,
                                              const float* __restrict__ w_ih_b,
                                              const float* __restrict__ b_b) {
    int d = blockIdx.z;
    const float* W    = d ? w_ih_b : w_ih_f;
    const float* bias = d ? b_b    : b_f;

    __shared__ float As[BK][BM];
    __shared__ float Bs[BK][BN];

    int tid = threadIdx.x;
    int tx = tid & 15, ty = tid >> 4;
    int t0 = blockIdx.y * BM, r0 = blockIdx.x * BN;

    unsigned long long acc2[8][4];
#pragma unroll
    for (int i = 0; i < 8; i++)
#pragma unroll
        for (int j = 0; j < 4; j++) acc2[i][j] = 0ull;

    int lm = tid >> 2;            // 0..63
    int lk = (tid & 3) * 4;       // 0,4,8,12

    for (int k0 = 0; k0 < E; k0 += BK) {
#pragma unroll
        for (int rep = 0; rep < 2; rep++) {
            float4 v = *(const float4*)(g_x + (size_t)(t0 + lm + rep * 64) * E + k0 + lk);
            As[lk + 0][lm + rep * 64] = v.x;
            As[lk + 1][lm + rep * 64] = v.y;
            As[lk + 2][lm + rep * 64] = v.z;
            As[lk + 3][lm + rep * 64] = v.w;
            float4 w = *(const float4*)(W + (size_t)(r0 + lm + rep * 64) * E + k0 + lk);
            Bs[lk + 0][lm + rep * 64] = w.x;
            Bs[lk + 1][lm + rep * 64] = w.y;
            Bs[lk + 2][lm + rep * 64] = w.z;
            Bs[lk + 3][lm + rep * 64] = w.w;
        }
        __syncthreads();
#pragma unroll
        for (int k = 0; k < BK; k++) {
            float a[8];
            *(float4*)(a)     = *(const float4*)&As[k][ty * 8];
            *(float4*)(a + 4) = *(const float4*)&As[k][ty * 8 + 4];
            ulonglong2 bl = *(const ulonglong2*)&Bs[k][tx * 8];
            ulonglong2 bh = *(const ulonglong2*)&Bs[k][tx * 8 + 4];
            unsigned long long bq[4] = {bl.x, bl.y, bh.x, bh.y};
#pragma unroll
            for (int i = 0; i < 8; i++) {
                unsigned long long ad;
                PACK2(ad, a[i], a[i]);
                FMA2(acc2[i][0], ad, bq[0]);
                FMA2(acc2[i][1], ad, bq[1]);
                FMA2(acc2[i][2], ad, bq[2]);
                FMA2(acc2[i][3], ad, bq[3]);
            }
        }
        __syncthreads();
    }

    float* out = g_xg[d];
#pragma unroll
    for (int i = 0; i < 8; i++) {
        int t = t0 + ty * 8 + i;
#pragma unroll
        for (int jp = 0; jp < 4; jp += 2) {
            int r = r0 + tx * 8 + jp * 2;
            float4 v;
            v.x = __uint_as_float((unsigned)(acc2[i][jp]     & 0xFFFFFFFFull)) + bias[r + 0];
            v.y = __uint_as_float((unsigned)(acc2[i][jp]     >> 32))           + bias[r + 1];
            v.z = __uint_as_float((unsigned)(acc2[i][jp + 1] & 0xFFFFFFFFull)) + bias[r + 2];
            v.w = __uint_as_float((unsigned)(acc2[i][jp + 1] >> 32))           + bias[r + 3];
            *(float4*)(out + (size_t)t * G4 + r) = v;
        }
    }
}

// ---------------- persistent bidirectional LSTM recurrence ----------------
// 128 CTAs x 288 threads. CTA (d*64+b) owns h[8b,8b+8) of direction d.
// Warps 0-7 (producers): poll own 64-col segment of h_prev (one v2 volatile
// load per thread -> 2KB/CTA/iter, far under the LTS cap), stage to smem,
// packed-f32x2 dot with register-resident W_hh, volatile-STS partial into
// the step-parity buffer. NO barriers.
// Warp 8 (reducer): spins on canary-poisoned partials (29-cyc smem
// granularity), sums, activations, publishes h (data-as-flag), re-poisons
// the consumed buffer before publishing (gates producers' step+2 writes).
__device__ __forceinline__ float sig_f(float x) { return 1.f / (1.f + __expf(-x)); }
__device__ __forceinline__ float tanh_f(float x) { return 1.f - 2.f / (__expf(2.f * x) + 1.f); }

__global__ void __launch_bounds__(288, 1) k_lstm(const float* __restrict__ w_hh_f,
                                                 const float* __restrict__ w_hh_b,
                                                 const float* __restrict__ h0,
                                                 const float* __restrict__ c0) {
    int cta = blockIdx.x;
    int d = cta >> 6;
    int b = cta & 63;
    const float* Whh = d ? w_hh_b : w_hh_f;

    int tid  = threadIdx.x;
    int wid  = tid >> 5;
    int lane = tid & 31;

    __shared__ float    sh_h[HD];
    __shared__ unsigned sh_part[2][8 * 32];   // [parity][seg*32 + gate-row]

    // poison both partial buffers once, then one block sync
    if (tid < 256) {
        sh_part[0][tid] = CANARY;
        sh_part[1][tid] = CANARY;
    }
    __syncthreads();

    float* hout = g_h[d];

    if (wid < 8) {
        // ---------------- producer warp ----------------
        int seg  = wid;
        int gate = lane >> 3, jj = lane & 7;
        int grow = gate * HD + b * 8 + jj;

        unsigned long long wq[32];
        {
            const ulonglong2* wr = (const ulonglong2*)(Whh + (size_t)grow * HD + seg * 64);
#pragma unroll
            for (int m = 0; m < 16; m++) {
                ulonglong2 v = wr[m];
                wq[2 * m] = v.x; wq[2 * m + 1] = v.y;
            }
        }

        for (int s = 0; s < T; s++) {
            int t = d ? (T - 1 - s) : s;
            float2 hv;
            if (s == 0) {
                hv = *(const float2*)(h0 + d * HD + seg * 64 + lane * 2);
            } else {
                int tp = d ? (t + 1) : (t - 1);
                const float* hp = hout + (size_t)tp * HD + seg * 64 + lane * 2;
                unsigned a, bb;
                do {
                    asm volatile("ld.volatile.global.v2.u32 {%0, %1}, [%2];"
                                 : "=r"(a), "=r"(bb) : "l"(hp));
                } while (a == CANARY || bb == CANARY);
                hv.x = __uint_as_float(a);
                hv.y = __uint_as_float(bb);
            }
            sh_h[seg * 64 + lane * 2]     = hv.x;
            sh_h[seg * 64 + lane * 2 + 1] = hv.y;
            __syncwarp();

            unsigned long long a0 = 0, a1 = 0, a2 = 0, a3 = 0;
            const ulonglong2* hq = (const ulonglong2*)(sh_h + seg * 64);
#pragma unroll
            for (int m = 0; m < 16; m += 2) {
                ulonglong2 x = hq[m];
                ulonglong2 y = hq[m + 1];
                FMA2(a0, wq[2 * m],     x.x);
                FMA2(a1, wq[2 * m + 1], x.y);
                FMA2(a2, wq[2 * m + 2], y.x);
                FMA2(a3, wq[2 * m + 3], y.y);
            }
            ADD2(a0, a2);
            ADD2(a1, a3);
            ADD2(a0, a1);
            float part = __uint_as_float((unsigned)(a0 & 0xFFFFFFFFull)) +
                         __uint_as_float((unsigned)(a0 >> 32));
            // publish partial: volatile STS is the flag (buffer pre-poisoned)
            ((volatile unsigned*)sh_part[s & 1])[seg * 32 + lane] = __float_as_uint(part);
        }
    } else {
        // ---------------- reducer warp ----------------
        int gate = lane >> 3, jj = lane & 7;
        int grow = gate * HD + b * 8 + jj;
        const float* xg = g_xg[d];

        float c = 0.f;
        if (lane < 8) c = c0[d * HD + b * 8 + lane];

        int t0i = d ? (T - 1) : 0;
        float xg_cur = __ldg(xg + (size_t)t0i * G4 + grow);

        for (int s = 0; s < T; s++) {
            int t = d ? (T - 1 - s) : s;
            volatile unsigned* sp = sh_part[s & 1];

            // spin until all 8 partials for my gate-row are real
            unsigned u[8];
            bool ok;
            do {
                ok = true;
#pragma unroll
                for (int p = 0; p < 8; p++) {
                    u[p] = sp[p * 32 + lane];
                    ok &= (u[p] != CANARY);
                }
            } while (!ok);

            // re-poison consumed buffer BEFORE publishing h[t]
#pragma unroll
            for (int p = 0; p < 8; p++) sp[p * 32 + lane] = CANARY;

            float xg_use = xg_cur;
            if (s + 1 < T) {
                int tn = d ? (t - 1) : (t + 1);
                xg_cur = __ldg(xg + (size_t)tn * G4 + grow);
            }

            float t0a = __uint_as_float(u[0]) + __uint_as_float(u[1]);
            float t1a = __uint_as_float(u[2]) + __uint_as_float(u[3]);
            float t2a = __uint_as_float(u[4]) + __uint_as_float(u[5]);
            float t3a = __uint_as_float(u[6]) + __uint_as_float(u[7]);
            float tot = xg_use + ((t0a + t1a) + (t2a + t3a));

            unsigned m = 0xFFFFFFFFu;
            float xi  = __shfl_sync(m, tot, (lane & 7));
            float xf  = __shfl_sync(m, tot, 8 + (lane & 7));
            float xgg = __shfl_sync(m, tot, 16 + (lane & 7));
            float xo  = __shfl_sync(m, tot, 24 + (lane & 7));
            if (lane < 8) {
                c = sig_f(xf) * c + sig_f(xi) * tanh_f(xgg);
                float hnew = sig_f(xo) * tanh_f(c);
                asm volatile("st.volatile.global.f32 [%0], %1;"
                             :: "l"(hout + (size_t)t * HD + b * 8 + lane), "f"(hnew));
            }
        }
    }
}

// ---------------- emissions: feats = [hf|hb] @ W_out^T + b_out ----------------
// 128 blocks x 512 threads, 16 timesteps per block. W_out chunk per thread in
// registers; h staged in ONE padded smem array (16 segs x stride 68 = 1088
// floats; broadcast across tags); shfl-xor reduce over 16 threads per tag.
#define FB 16
__global__ void __launch_bounds__(512) k_feats(const float* __restrict__ W_out,
                                               const float* __restrict__ b_out) {
    __shared__ float shp[16 * 68];   // single array: 1024 cols padded to 1088

    int tid = threadIdx.x;
    int tag = tid >> 4, q = tid & 15;

    float4 wr[16];
    const float4* wp = (const float4*)(W_out + (size_t)tag * 1024 + q * 64);
#pragma unroll
    for (int i = 0; i < 16; i++) wr[i] = wp[i];
    float bias = b_out[tag];

    int c  = tid * 2;
    int cs = (c >> 6) * 68 + (c & 63);
    int t0 = blockIdx.x * FB;

    for (int i = 0; i < FB; i++) {
        int t = t0 + i;
        const float* src = (c < 512) ? (g_h[0] + (size_t)t * HD + c)
                                     : (g_h[1] + (size_t)t * HD + (c - 512));
        float2 hv = *(const float2*)src;
        __syncthreads();              // previous compute done before overwrite
        shp[cs]     = hv.x;
        shp[cs + 1] = hv.y;
        __syncthreads();

        const float4* hq = (const float4*)&shp[q * 68];
        float s = 0.f;
#pragma unroll
        for (int k2 = 0; k2 < 16; k2++) {
            float4 h4 = hq[k2];
            float4 w4 = wr[k2];
            s += w4.x * h4.x + w4.y * h4.y + w4.z * h4.z + w4.w * h4.w;
        }
        s += __shfl_xor_sync(0xFFFFFFFFu, s, 1);
        s += __shfl_xor_sync(0xFFFFFFFFu, s, 2);
        s += __shfl_xor_sync(0xFFFFFFFFu, s, 4);
        s += __shfl_xor_sync(0xFFFFFFFFu, s, 8);
        if (q == 0) g_feats[t * TAGS + tag] = s + bias;
    }
}

// ---------------- Viterbi (single warp; strict-greater first-max argmax) -----
extern __shared__ unsigned char vit_smem[];
__global__ void k_viterbi(const float* __restrict__ transitions, float* __restrict__ out,
                          int out_size) {
    unsigned char* bp = vit_smem;                    // T*TAGS bytes
    float* fvbuf = (float*)(vit_smem + T * TAGS);    // 2 * TAGS floats (ping-pong)
    int n = threadIdx.x;

    float tr[TAGS];
#pragma unroll
    for (int j = 0; j < TAGS; j++) tr[j] = transitions[n * TAGS + j];

    fvbuf[n] = (n == START) ? 0.f : NEGV;
    __syncwarp();

    float f0 = g_feats[0 * TAGS + n];
    float f1 = g_feats[1 * TAGS + n];

    for (int t = 0; t < T; t++) {
        const float* fv = fvbuf + (t & 1) * TAGS;
        float*       fw = fvbuf + ((t + 1) & 1) * TAGS;

        float b0, b1, b2, b3;
        int   a0 = 0, a1 = 8, a2 = 16, a3 = 24;
        b0 = fv[0]  + tr[0];
        b1 = fv[8]  + tr[8];
        b2 = fv[16] + tr[16];
        b3 = fv[24] + tr[24];
#pragma unroll
        for (int j = 1; j < 8; j++) {
            float v0 = fv[j]      + tr[j];
            float v1 = fv[j + 8]  + tr[j + 8];
            float v2 = fv[j + 16] + tr[j + 16];
            float v3 = fv[j + 24] + tr[j + 24];
            if (v0 > b0) { b0 = v0; a0 = j; }
            if (v1 > b1) { b1 = v1; a1 = j + 8; }
            if (v2 > b2) { b2 = v2; a2 = j + 16; }
            if (v3 > b3) { b3 = v3; a3 = j + 24; }
        }
        if (b1 > b0) { b0 = b1; a0 = a1; }
        if (b3 > b2) { b2 = b3; a2 = a3; }
        if (b2 > b0) { b0 = b2; a0 = a2; }

        float feat = (t & 1) ? f1 : f0;
        if (t + 2 < T) {
            float nf = g_feats[(t + 2) * TAGS + n];
            if (t & 1) f1 = nf; else f0 = nf;
        }
        bp[t * TAGS + n] = (unsigned char)a0;
        fw[n] = b0 + feat;
        __syncwarp();
    }

    const float* fvF = fvbuf + (T & 1) * TAGS;
    float term = fvF[n] + transitions[STOP * TAGS + n];
    int best = 0;
    {
        float bb = __shfl_sync(0xFFFFFFFFu, term, 0);
#pragma unroll
        for (int j = 1; j < TAGS; j++) {
            float v = __shfl_sync(0xFFFFFFFFu, term, j);
            if (v > bb) { bb = v; best = j; }
        }
    }
    float score = fvF[best] + transitions[STOP * TAGS + best];

    if (n == 0) {
        if (out_size >= T + 1) {
            out[0] = score;
            int tag = best;
            for (int t = T - 1; t >= 0; t--) {
                out[1 + t] = (float)tag;
                tag = bp[t * TAGS + tag];
            }
        } else if (out_size >= T) {
            int tag = best;
            for (int t = T - 1; t >= 0; t--) {
                out[t] = (float)tag;
                tag = bp[t * TAGS + tag];
            }
        } else {
            out[0] = score;
        }
    }
}

// ---------------- launch ----------------
extern "C" void kernel_launch(void* const* d_in, const int* in_sizes, int n_in,
                              void* d_out, int out_size) {
    const int*   sentence    = (const int*)d_in[0];
    const float* emb         = (const float*)d_in[1];
    const float* w_ih_f      = (const float*)d_in[2];
    const float* w_hh_f      = (const float*)d_in[3];
    const float* b_f         = (const float*)d_in[4];
    const float* w_ih_b      = (const float*)d_in[5];
    const float* w_hh_b      = (const float*)d_in[6];
    const float* b_b         = (const float*)d_in[7];
    const float* W_out       = (const float*)d_in[8];
    const float* b_out       = (const float*)d_in[9];
    const float* transitions = (const float*)d_in[10];
    const float* h0          = (const float*)d_in[11];
    const float* c0          = (const float*)d_in[12];
    float* out = (float*)d_out;

    k_prep<<<T + 2048, 128>>>(sentence, emb);
    k_gemm<<<dim3(16, 16, 2), 256>>>(w_ih_f, b_f, w_ih_b, b_b);
    k_lstm<<<128, 288>>>(w_hh_f, w_hh_b, h0, c0);
    k_feats<<<128, 512>>>(W_out, b_out);

    int vit_smem_bytes = T * TAGS + 2 * TAGS * (int)sizeof(float);
    cudaFuncSetAttribute(k_viterbi, cudaFuncAttributeMaxDynamicSharedMemorySize, vit_smem_bytes);
    k_viterbi<<<1, 32, vit_smem_bytes>>>(transitions, out, out_size);
}